// round 13
// baseline (speedup 1.0000x reference)
#include <cuda_runtime.h>
#include <cstdint>

#define EPS     1e-6f
#define MARGIN  0.5f
#define D       128
#define TPB     128
#define WPB     4                // warps per block
#define BATCH   3                // triplets per warp per stage
#define STAGES  2                // double-buffer
#define ROWS    (BATCH * 3)      // 9 gathered rows per stage
#define ROW_B   512              // bytes per row (128 floats)
#define STAGE_B (ROWS * ROW_B)   // 4608 B per warp-stage
#define WARP_B  (STAGES * STAGE_B)   // 9216 B
#define SMEM_B  (WPB * WARP_B)   // 36864 B per block -> 6 blocks/SM
#define MAXBLK  4096

static __device__ float        g_partial[MAXBLK];
static __device__ unsigned int g_ticket;

__device__ __forceinline__ float fsqrt_approx(float x)
{
    float r;
    asm("sqrt.approx.f32 %0, %1;" : "=f"(r) : "f"(x));
    return r;
}

__device__ __forceinline__ uint32_t smem_u32(const void* p)
{
    uint32_t a;
    asm("{ .reg .u64 t; cvta.to.shared.u64 t, %1; cvt.u32.u64 %0, t; }"
        : "=r"(a) : "l"(p));
    return a;
}

__device__ __forceinline__ void cp_async16(uint32_t dst, const void* src)
{
    asm volatile("cp.async.cg.shared.global [%0], [%1], 16;"
                 :: "r"(dst), "l"(src) : "memory");
}

#define CP_COMMIT() asm volatile("cp.async.commit_group;" ::: "memory")
#define CP_WAIT(n)  asm volatile("cp.async.wait_group %0;" :: "n"(n) : "memory")

struct IdxSet { int ia[BATCH], ip[BATCH], in[BATCH]; };

// Load indices for the batch at t; only rows with t+k < end are needed.
__device__ __forceinline__ void load_indices(const int* __restrict__ ai,
                                             const int* __restrict__ pi,
                                             const int* __restrict__ ni,
                                             int t, int end, IdxSet& S)
{
    #pragma unroll
    for (int k = 0; k < BATCH; k++) {
        const int ix = (t + k < end) ? (t + k) : t;   // clamp (in-bounds, masked later)
        S.ia[k] = __ldg(ai + ix);
        S.ip[k] = __ldg(pi + ix);
        S.in[k] = __ldg(ni + ix);
    }
}

// Issue cp.asyncs for one stage; skip rows beyond `end` (no wasted bandwidth).
// Always commits a group (possibly empty) to keep wait_group accounting uniform.
__device__ __forceinline__ void fill_stage(const float* __restrict__ emb,
                                           const IdxSet& S, int t, int end,
                                           int lane, uint32_t warp_smem, int stage)
{
    const uint32_t sbase = warp_smem + stage * STAGE_B + lane * 16;
    #pragma unroll
    for (int k = 0; k < BATCH; k++) {
        if (t + k < end) {      // warp-uniform
            cp_async16(sbase + (k * 3 + 0) * ROW_B,
                       (const float4*)(emb + (size_t)S.ia[k] * D) + lane);
            cp_async16(sbase + (k * 3 + 1) * ROW_B,
                       (const float4*)(emb + (size_t)S.ip[k] * D) + lane);
            cp_async16(sbase + (k * 3 + 2) * ROW_B,
                       (const float4*)(emb + (size_t)S.in[k] * D) + lane);
        }
    }
    CP_COMMIT();
}

// Hybrid folding butterfly for BATCH=3 (15 SHFLs, 2 MUFU sqrt):
//  - triplets 0,1 folded into lane bits {bit4 = kind, bit3 = trip}: 8 dup
//    kind0 lanes per triplet (weight 1/8)
//  - triplet 2 kind-folded then plain butterfly: 16 dup kind0 lanes (1/16)
// Garbage in masked-out triplets stays confined to its own fold chain and is
// excluded by the validity branches. Returns pre-weighted contribution.
__device__ __forceinline__ float compute_stage(int t, int end, int lane,
                                               uint32_t warp_smem, int stage)
{
    const uint32_t sbase = warp_smem + stage * STAGE_B + lane * 16;

    float sp[BATCH], sn[BATCH];
    #pragma unroll
    for (int k = 0; k < BATCH; k++) {
        float4 a, p, n;
        asm volatile("ld.shared.v4.f32 {%0,%1,%2,%3}, [%4];"
                     : "=f"(a.x), "=f"(a.y), "=f"(a.z), "=f"(a.w)
                     : "r"(sbase + (k * 3 + 0) * ROW_B));
        asm volatile("ld.shared.v4.f32 {%0,%1,%2,%3}, [%4];"
                     : "=f"(p.x), "=f"(p.y), "=f"(p.z), "=f"(p.w)
                     : "r"(sbase + (k * 3 + 1) * ROW_B));
        asm volatile("ld.shared.v4.f32 {%0,%1,%2,%3}, [%4];"
                     : "=f"(n.x), "=f"(n.y), "=f"(n.z), "=f"(n.w)
                     : "r"(sbase + (k * 3 + 2) * ROW_B));
        float d, s0 = 0.0f, s1 = 0.0f;
        d = a.x - p.x + EPS; s0 += d * d;
        d = a.y - p.y + EPS; s0 += d * d;
        d = a.z - p.z + EPS; s0 += d * d;
        d = a.w - p.w + EPS; s0 += d * d;
        d = a.x - n.x + EPS; s1 += d * d;
        d = a.y - n.y + EPS; s1 += d * d;
        d = a.z - n.z + EPS; s1 += d * d;
        d = a.w - n.w + EPS; s1 += d * d;
        sp[k] = s0; sn[k] = s1;
    }

    const unsigned FULL = 0xFFFFFFFFu;
    // off=16: fold kind (sp_k with sn_k), 6 shfl -> w[0..2]
    float w[3];
    #pragma unroll
    for (int k = 0; k < 3; k++) {
        float a  = sp[k], b = sn[k];
        float a2 = __shfl_xor_sync(FULL, a, 16);
        float b2 = __shfl_xor_sync(FULL, b, 16);
        w[k] = (lane & 16) ? (b + b2) : (a + a2);
    }
    // off=8: fold trip (w0 with w1), 2 shfl; w2 plain, 1 shfl
    float x;
    {
        float a  = w[0], b = w[1];
        float a2 = __shfl_xor_sync(FULL, a, 8);
        float b2 = __shfl_xor_sync(FULL, b, 8);
        x = (lane & 8) ? (b + b2) : (a + a2);
        w[2] += __shfl_xor_sync(FULL, w[2], 8);
    }
    // off=4,2,1: plain butterfly on both, 6 shfl
    x    += __shfl_xor_sync(FULL, x, 4);
    w[2] += __shfl_xor_sync(FULL, w[2], 4);
    x    += __shfl_xor_sync(FULL, x, 2);
    w[2] += __shfl_xor_sync(FULL, w[2], 2);
    x    += __shfl_xor_sync(FULL, x, 1);
    w[2] += __shfl_xor_sync(FULL, w[2], 1);

    const float r01  = fsqrt_approx(x);
    const float rn01 = __shfl_xor_sync(FULL, r01, 16);
    const float r2   = fsqrt_approx(w[2]);
    const float rn2  = __shfl_xor_sync(FULL, r2, 16);

    const int  trip  = (lane >> 3) & 1;
    const bool kind0 = (lane & 16) == 0;

    float c = 0.0f;
    if (kind0) {
        if (t + trip < end)
            c += 0.125f  * fmaxf(r01 - rn01 + MARGIN, 0.0f);
        if (t + 2 < end)
            c += 0.0625f * fmaxf(r2  - rn2  + MARGIN, 0.0f);
    }
    return c;
}

__global__ void __launch_bounds__(TPB)
triplet_kernel(const float* __restrict__ emb,
               const int*   __restrict__ a_idx,
               const int*   __restrict__ p_idx,
               const int*   __restrict__ n_idx,
               float* __restrict__ out,
               int T, int nblocks)
{
    extern __shared__ char smem[];
    const int lane  = threadIdx.x & 31;
    const int w     = threadIdx.x >> 5;
    const int gw    = blockIdx.x * WPB + w;
    const int nwarp = nblocks * WPB;
    const uint32_t warp_smem = smem_u32(smem) + w * WARP_B;

    // Contiguous per-warp range, balanced to +-1 triplet.
    const int base = (int)(((long long)gw       * T) / nwarp);
    const int end  = (int)(((long long)(gw + 1) * T) / nwarp);

    float acc = 0.0f;

    if (base < end) {
        const int n_it = (end - base + BATCH - 1) / BATCH;
        const int nfill = (n_it < STAGES) ? n_it : STAGES;

        // Prologue: fill up to STAGES stages ahead.
        for (int s = 0; s < nfill; s++) {
            IdxSet S;
            load_indices(a_idx, p_idx, n_idx, base + s * BATCH, end, S);
            fill_stage(emb, S, base + s * BATCH, end, lane, warp_smem, s);
        }

        // Index pipeline: idx_cur holds indices for the refill issued at iter i.
        IdxSet idx_cur;
        if (n_it > STAGES)
            load_indices(a_idx, p_idx, n_idx, base + STAGES * BATCH, end, idx_cur);

        int t = base;
        for (int i = 0; i < n_it; i++, t += BATCH) {
            // Prefetch indices for next iteration's refill (hidden under compute).
            IdxSet idx_next;
            const int t_next_fill = t + (STAGES + 1) * BATCH;
            if (t_next_fill < end)
                load_indices(a_idx, p_idx, n_idx, t_next_fill, end, idx_next);

            // Wait until iteration i's group has landed.
            const int rem = n_it - 1 - i;
            if (rem >= STAGES - 1) CP_WAIT(STAGES - 1);
            else                   CP_WAIT(0);

            acc += compute_stage(t, end, lane, warp_smem, i % STAGES);

            // Refill the just-freed stage using pre-loaded indices.
            const int t_fill = t + STAGES * BATCH;
            if (t_fill < end)
                fill_stage(emb, idx_cur, t_fill, end, lane, warp_smem, i % STAGES);

            idx_cur = idx_next;
        }
    }

    // Final per-warp reduction of the non-uniform pre-weighted accumulator.
    const unsigned FULL = 0xFFFFFFFFu;
    #pragma unroll
    for (int off = 16; off > 0; off >>= 1)
        acc += __shfl_xor_sync(FULL, acc, off);

    // ---- block reduction, fixed order -> deterministic ----
    __shared__ float ws[WPB];
    __shared__ bool  is_last;
    if (lane == 0) ws[w] = acc;
    __syncthreads();
    if (threadIdx.x == 0) {
        float s = 0.0f;
        #pragma unroll
        for (int i = 0; i < WPB; i++) s += ws[i];
        g_partial[blockIdx.x] = s;
        __threadfence();
        unsigned int done = atomicAdd(&g_ticket, 1u);
        is_last = (done == (unsigned)(nblocks - 1));
    }
    __syncthreads();

    // ---- last block folds all partials: deterministic fixed-order tree ----
    if (is_last) {
        __shared__ float sh[TPB];
        float s = 0.0f;
        for (int i = threadIdx.x; i < nblocks; i += TPB)
            s += g_partial[i];
        sh[threadIdx.x] = s;
        __syncthreads();
        #pragma unroll
        for (int off = TPB / 2; off > 0; off >>= 1) {
            if (threadIdx.x < off) sh[threadIdx.x] += sh[threadIdx.x + off];
            __syncthreads();
        }
        if (threadIdx.x == 0) {
            out[0] = sh[0] / (float)T;
            g_ticket = 0;          // reset for next graph replay
        }
    }
}

extern "C" void kernel_launch(void* const* d_in, const int* in_sizes, int n_in,
                              void* d_out, int out_size)
{
    const float* emb   = (const float*)d_in[0];
    const int*   a_idx = (const int*)d_in[2];
    const int*   p_idx = (const int*)d_in[3];
    const int*   n_idx = (const int*)d_in[4];
    float*       out   = (float*)d_out;

    const int T = in_sizes[2];

    cudaFuncSetAttribute(triplet_kernel,
                         cudaFuncAttributeMaxDynamicSharedMemorySize, SMEM_B);

    int dev = 0, nsm = 148, bpm = 6;
    cudaGetDevice(&dev);
    cudaDeviceGetAttribute(&nsm, cudaDevAttrMultiProcessorCount, dev);
    cudaOccupancyMaxActiveBlocksPerMultiprocessor(&bpm, triplet_kernel, TPB, SMEM_B);
    if (bpm < 1) bpm = 1;
    int nblocks = nsm * bpm;
    if (nblocks > MAXBLK) nblocks = MAXBLK;

    triplet_kernel<<<nblocks, TPB, SMEM_B>>>(emb, a_idx, p_idx, n_idx, out, T, nblocks);
}

// round 14
// speedup vs baseline: 1.0164x; 1.0164x over previous
#include <cuda_runtime.h>
#include <cstdint>

#define EPS     1e-6f
#define MARGIN  0.5f
#define D       128
#define TPB     128
#define WPB     4                // warps per block
#define BATCH   3                // triplets per warp per stage
#define STAGES  2                // double-buffer
#define ROWS    (BATCH * 3)      // 9 gathered rows per stage
#define ROW_B   512              // bytes per row (128 floats)
#define STAGE_B (ROWS * ROW_B)   // 4608 B per warp-stage
#define WARP_B  (STAGES * STAGE_B)   // 9216 B
#define SMEM_B  (WPB * WARP_B)   // 36864 B per block -> 6 blocks/SM
#define MAXBLK  4096

static __device__ float        g_partial[MAXBLK];
static __device__ unsigned int g_ticket;

__device__ __forceinline__ float fsqrt_approx(float x)
{
    float r;
    asm("sqrt.approx.f32 %0, %1;" : "=f"(r) : "f"(x));
    return r;
}

__device__ __forceinline__ uint32_t smem_u32(const void* p)
{
    uint32_t a;
    asm("{ .reg .u64 t; cvta.to.shared.u64 t, %1; cvt.u32.u64 %0, t; }"
        : "=r"(a) : "l"(p));
    return a;
}

__device__ __forceinline__ void cp_async16(uint32_t dst, const void* src)
{
    asm volatile("cp.async.cg.shared.global [%0], [%1], 16;"
                 :: "r"(dst), "l"(src) : "memory");
}

#define CP_COMMIT() asm volatile("cp.async.commit_group;" ::: "memory")
#define CP_WAIT(n)  asm volatile("cp.async.wait_group %0;" :: "n"(n) : "memory")

struct IdxSet { int ia[BATCH], ip[BATCH], in[BATCH]; };

__device__ __forceinline__ void load_indices(const int* __restrict__ ai,
                                             const int* __restrict__ pi,
                                             const int* __restrict__ ni,
                                             int t, int T, IdxSet& S)
{
    #pragma unroll
    for (int k = 0; k < BATCH; k++) {
        const int ix = (t + k < T) ? (t + k) : 0;
        S.ia[k] = __ldg(ai + ix);
        S.ip[k] = __ldg(pi + ix);
        S.in[k] = __ldg(ni + ix);
    }
}

// Issue 9 cp.asyncs for one stage using ALREADY-LOADED indices.
__device__ __forceinline__ void fill_stage(const float* __restrict__ emb,
                                           const IdxSet& S, int lane,
                                           uint32_t warp_smem, int stage)
{
    const uint32_t sbase = warp_smem + stage * STAGE_B + lane * 16;
    #pragma unroll
    for (int k = 0; k < BATCH; k++) {
        cp_async16(sbase + (k * 3 + 0) * ROW_B,
                   (const float4*)(emb + (size_t)S.ia[k] * D) + lane);
        cp_async16(sbase + (k * 3 + 1) * ROW_B,
                   (const float4*)(emb + (size_t)S.ip[k] * D) + lane);
        cp_async16(sbase + (k * 3 + 2) * ROW_B,
                   (const float4*)(emb + (size_t)S.in[k] * D) + lane);
    }
    CP_COMMIT();
}

// Hybrid folding butterfly for BATCH=3 (15 SHFLs, 2 MUFU sqrt):
//  - triplets 0,1 folded into lane bits {bit4 = kind, bit3 = trip}: 8 dup
//    kind0 lanes per triplet (weight 1/8)
//  - triplet 2 kind-folded then plain butterfly: 16 dup kind0 lanes (1/16)
// Returns this lane's (non-uniform) pre-weighted loss contribution.
__device__ __forceinline__ float compute_stage(int t, int T, int lane,
                                               uint32_t warp_smem, int stage)
{
    const uint32_t sbase = warp_smem + stage * STAGE_B + lane * 16;

    float sp[BATCH], sn[BATCH];
    #pragma unroll
    for (int k = 0; k < BATCH; k++) {
        float4 a, p, n;
        asm volatile("ld.shared.v4.f32 {%0,%1,%2,%3}, [%4];"
                     : "=f"(a.x), "=f"(a.y), "=f"(a.z), "=f"(a.w)
                     : "r"(sbase + (k * 3 + 0) * ROW_B));
        asm volatile("ld.shared.v4.f32 {%0,%1,%2,%3}, [%4];"
                     : "=f"(p.x), "=f"(p.y), "=f"(p.z), "=f"(p.w)
                     : "r"(sbase + (k * 3 + 1) * ROW_B));
        asm volatile("ld.shared.v4.f32 {%0,%1,%2,%3}, [%4];"
                     : "=f"(n.x), "=f"(n.y), "=f"(n.z), "=f"(n.w)
                     : "r"(sbase + (k * 3 + 2) * ROW_B));
        float d, s0 = 0.0f, s1 = 0.0f;
        d = a.x - p.x + EPS; s0 += d * d;
        d = a.y - p.y + EPS; s0 += d * d;
        d = a.z - p.z + EPS; s0 += d * d;
        d = a.w - p.w + EPS; s0 += d * d;
        d = a.x - n.x + EPS; s1 += d * d;
        d = a.y - n.y + EPS; s1 += d * d;
        d = a.z - n.z + EPS; s1 += d * d;
        d = a.w - n.w + EPS; s1 += d * d;
        sp[k] = s0; sn[k] = s1;
    }

    const unsigned FULL = 0xFFFFFFFFu;
    // off=16: fold kind (sp_k with sn_k), 6 shfl -> w[0..2]
    float w[3];
    #pragma unroll
    for (int k = 0; k < 3; k++) {
        float a  = sp[k], b = sn[k];
        float a2 = __shfl_xor_sync(FULL, a, 16);
        float b2 = __shfl_xor_sync(FULL, b, 16);
        w[k] = (lane & 16) ? (b + b2) : (a + a2);
    }
    // off=8: fold trip (w0 with w1), 2 shfl; w2 plain, 1 shfl
    float x;
    {
        float a  = w[0], b = w[1];
        float a2 = __shfl_xor_sync(FULL, a, 8);
        float b2 = __shfl_xor_sync(FULL, b, 8);
        x = (lane & 8) ? (b + b2) : (a + a2);
        w[2] += __shfl_xor_sync(FULL, w[2], 8);
    }
    // off=4,2,1: plain butterfly on both, 6 shfl
    x    += __shfl_xor_sync(FULL, x, 4);
    w[2] += __shfl_xor_sync(FULL, w[2], 4);
    x    += __shfl_xor_sync(FULL, x, 2);
    w[2] += __shfl_xor_sync(FULL, w[2], 2);
    x    += __shfl_xor_sync(FULL, x, 1);
    w[2] += __shfl_xor_sync(FULL, w[2], 1);

    const float r01  = fsqrt_approx(x);
    const float rn01 = __shfl_xor_sync(FULL, r01, 16);
    const float r2   = fsqrt_approx(w[2]);
    const float rn2  = __shfl_xor_sync(FULL, r2, 16);

    const int  trip  = (lane >> 3) & 1;
    const bool kind0 = (lane & 16) == 0;

    float c = 0.0f;
    if (kind0) {
        if (t + trip < T)
            c += 0.125f  * fmaxf(r01 - rn01 + MARGIN, 0.0f);
        if (t + 2 < T)
            c += 0.0625f * fmaxf(r2  - rn2  + MARGIN, 0.0f);
    }
    return c;
}

__global__ void __launch_bounds__(TPB)
triplet_kernel(const float* __restrict__ emb,
               const int*   __restrict__ a_idx,
               const int*   __restrict__ p_idx,
               const int*   __restrict__ n_idx,
               float* __restrict__ out,
               int T, int nblocks)
{
    extern __shared__ char smem[];
    const int lane   = threadIdx.x & 31;
    const int w      = threadIdx.x >> 5;
    const int gw     = blockIdx.x * WPB + w;
    const int stride = nblocks * WPB * BATCH;   // strided: narrow chip-wide t-window -> L2 reuse
    const uint32_t warp_smem = smem_u32(smem) + w * WARP_B;

    float acc = 0.0f;

    const int base_t = gw * BATCH;
    if (base_t < T) {
        const int n_it = (T - base_t + stride - 1) / stride;
        const int nfill = (n_it < STAGES) ? n_it : STAGES;

        // Prologue: fill up to STAGES stages ahead.
        for (int s = 0; s < nfill; s++) {
            IdxSet S;
            load_indices(a_idx, p_idx, n_idx, base_t + s * stride, T, S);
            fill_stage(emb, S, lane, warp_smem, s);
        }

        // 2x-unrolled ping-pong over two index register sets (no IdxSet copies).
        IdxSet ia_, ib_;
        if (n_it > STAGES)
            load_indices(a_idx, p_idx, n_idx, base_t + STAGES * stride, T, ia_);

        int t = base_t;
        int i = 0;
        while (i < n_it) {
            // --- even iteration: fill uses ia_, prefetch ib_ ---
            {
                const int tnf = t + (STAGES + 1) * stride;
                if (tnf < T)
                    load_indices(a_idx, p_idx, n_idx, tnf, T, ib_);

                if (i < n_it - 1) CP_WAIT(1);
                else              CP_WAIT(0);

                acc += compute_stage(t, T, lane, warp_smem, i & 1);

                if (t + STAGES * stride < T)
                    fill_stage(emb, ia_, lane, warp_smem, i & 1);

                i++; t += stride;
                if (i >= n_it) break;
            }
            // --- odd iteration: fill uses ib_, prefetch ia_ ---
            {
                const int tnf = t + (STAGES + 1) * stride;
                if (tnf < T)
                    load_indices(a_idx, p_idx, n_idx, tnf, T, ia_);

                if (i < n_it - 1) CP_WAIT(1);
                else              CP_WAIT(0);

                acc += compute_stage(t, T, lane, warp_smem, i & 1);

                if (t + STAGES * stride < T)
                    fill_stage(emb, ib_, lane, warp_smem, i & 1);

                i++; t += stride;
            }
        }
    }

    // Final per-warp reduction of the non-uniform pre-weighted accumulator.
    const unsigned FULL = 0xFFFFFFFFu;
    #pragma unroll
    for (int off = 16; off > 0; off >>= 1)
        acc += __shfl_xor_sync(FULL, acc, off);

    // ---- block reduction, fixed order -> deterministic ----
    __shared__ float ws[WPB];
    __shared__ bool  is_last;
    if (lane == 0) ws[w] = acc;
    __syncthreads();
    if (threadIdx.x == 0) {
        float s = 0.0f;
        #pragma unroll
        for (int i2 = 0; i2 < WPB; i2++) s += ws[i2];
        g_partial[blockIdx.x] = s;
        __threadfence();
        unsigned int done = atomicAdd(&g_ticket, 1u);
        is_last = (done == (unsigned)(nblocks - 1));
    }
    __syncthreads();

    // ---- last block folds all partials: deterministic fixed-order tree ----
    if (is_last) {
        __shared__ float sh[TPB];
        float s = 0.0f;
        for (int i2 = threadIdx.x; i2 < nblocks; i2 += TPB)
            s += g_partial[i2];
        sh[threadIdx.x] = s;
        __syncthreads();
        #pragma unroll
        for (int off = TPB / 2; off > 0; off >>= 1) {
            if (threadIdx.x < off) sh[threadIdx.x] += sh[threadIdx.x + off];
            __syncthreads();
        }
        if (threadIdx.x == 0) {
            out[0] = sh[0] / (float)T;
            g_ticket = 0;          // reset for next graph replay
        }
    }
}

extern "C" void kernel_launch(void* const* d_in, const int* in_sizes, int n_in,
                              void* d_out, int out_size)
{
    const float* emb   = (const float*)d_in[0];
    const int*   a_idx = (const int*)d_in[2];
    const int*   p_idx = (const int*)d_in[3];
    const int*   n_idx = (const int*)d_in[4];
    float*       out   = (float*)d_out;

    const int T = in_sizes[2];

    cudaFuncSetAttribute(triplet_kernel,
                         cudaFuncAttributeMaxDynamicSharedMemorySize, SMEM_B);

    int dev = 0, nsm = 148, bpm = 6;
    cudaGetDevice(&dev);
    cudaDeviceGetAttribute(&nsm, cudaDevAttrMultiProcessorCount, dev);
    cudaOccupancyMaxActiveBlocksPerMultiprocessor(&bpm, triplet_kernel, TPB, SMEM_B);
    if (bpm < 1) bpm = 1;
    int nblocks = nsm * bpm;
    if (nblocks > MAXBLK) nblocks = MAXBLK;

    triplet_kernel<<<nblocks, TPB, SMEM_B>>>(emb, a_idx, p_idx, n_idx, out, T, nblocks);
}

// round 15
// speedup vs baseline: 1.0500x; 1.0331x over previous
#include <cuda_runtime.h>
#include <cstdint>

#define EPS     1e-6f
#define MARGIN  0.5f
#define D       128
#define TPB     128
#define WPB     4                // warps per block
#define BATCH   4                // triplets per warp per stage
#define STAGES  2                // double-buffer
#define ROWS    (BATCH * 3)      // 12 gathered rows per stage
#define ROW_B   512              // bytes per row (128 floats)
#define STAGE_B (ROWS * ROW_B)   // 6144 B per warp-stage
#define WARP_B  (STAGES * STAGE_B)   // 12288 B
#define SMEM_B  (WPB * WARP_B)   // 49152 B per block -> 4 blocks/SM
#define MAXBLK  4096

static __device__ float        g_partial[MAXBLK];
static __device__ unsigned int g_ticket;

__device__ __forceinline__ float fsqrt_approx(float x)
{
    float r;
    asm("sqrt.approx.f32 %0, %1;" : "=f"(r) : "f"(x));
    return r;
}

__device__ __forceinline__ uint32_t smem_u32(const void* p)
{
    uint32_t a;
    asm("{ .reg .u64 t; cvta.to.shared.u64 t, %1; cvt.u32.u64 %0, t; }"
        : "=r"(a) : "l"(p));
    return a;
}

__device__ __forceinline__ void cp_async16(uint32_t dst, const void* src)
{
    asm volatile("cp.async.cg.shared.global [%0], [%1], 16;"
                 :: "r"(dst), "l"(src) : "memory");
}

#define CP_COMMIT() asm volatile("cp.async.commit_group;" ::: "memory")
#define CP_WAIT(n)  asm volatile("cp.async.wait_group %0;" :: "n"(n) : "memory")

struct IdxSet { int ia[BATCH], ip[BATCH], in[BATCH]; };

__device__ __forceinline__ void load_indices(const int* __restrict__ ai,
                                             const int* __restrict__ pi,
                                             const int* __restrict__ ni,
                                             int t, int T, IdxSet& S)
{
    #pragma unroll
    for (int k = 0; k < BATCH; k++) {
        const int ix = (t + k < T) ? (t + k) : 0;
        S.ia[k] = __ldg(ai + ix);
        S.ip[k] = __ldg(pi + ix);
        S.in[k] = __ldg(ni + ix);
    }
}

// Issue 12 cp.asyncs for one stage using ALREADY-LOADED indices.
__device__ __forceinline__ void fill_stage(const float* __restrict__ emb,
                                           const IdxSet& S, int lane,
                                           uint32_t warp_smem, int stage)
{
    const uint32_t sbase = warp_smem + stage * STAGE_B + lane * 16;
    #pragma unroll
    for (int k = 0; k < BATCH; k++) {
        cp_async16(sbase + (k * 3 + 0) * ROW_B,
                   (const float4*)(emb + (size_t)S.ia[k] * D) + lane);
        cp_async16(sbase + (k * 3 + 1) * ROW_B,
                   (const float4*)(emb + (size_t)S.ip[k] * D) + lane);
        cp_async16(sbase + (k * 3 + 2) * ROW_B,
                   (const float4*)(emb + (size_t)S.in[k] * D) + lane);
    }
    CP_COMMIT();
}

// Folding butterfly for BATCH=4: 8 per-lane partials -> one complete sum per
// lane in 16 SHFLs. kind = lane bit4 (0=sp), trip = (bit3<<1)|bit2.
// 4 duplicate kind0 lanes per triplet -> weight 0.25 applied here.
__device__ __forceinline__ float compute_stage(int t, int T, int lane,
                                               uint32_t warp_smem, int stage)
{
    const uint32_t sbase = warp_smem + stage * STAGE_B + lane * 16;

    float v[8];
    #pragma unroll
    for (int k = 0; k < BATCH; k++) {
        float4 a, p, n;
        asm volatile("ld.shared.v4.f32 {%0,%1,%2,%3}, [%4];"
                     : "=f"(a.x), "=f"(a.y), "=f"(a.z), "=f"(a.w)
                     : "r"(sbase + (k * 3 + 0) * ROW_B));
        asm volatile("ld.shared.v4.f32 {%0,%1,%2,%3}, [%4];"
                     : "=f"(p.x), "=f"(p.y), "=f"(p.z), "=f"(p.w)
                     : "r"(sbase + (k * 3 + 1) * ROW_B));
        asm volatile("ld.shared.v4.f32 {%0,%1,%2,%3}, [%4];"
                     : "=f"(n.x), "=f"(n.y), "=f"(n.z), "=f"(n.w)
                     : "r"(sbase + (k * 3 + 2) * ROW_B));
        float d, s0 = 0.0f, s1 = 0.0f;
        d = a.x - p.x + EPS; s0 += d * d;
        d = a.y - p.y + EPS; s0 += d * d;
        d = a.z - p.z + EPS; s0 += d * d;
        d = a.w - p.w + EPS; s0 += d * d;
        d = a.x - n.x + EPS; s1 += d * d;
        d = a.y - n.y + EPS; s1 += d * d;
        d = a.z - n.z + EPS; s1 += d * d;
        d = a.w - n.w + EPS; s1 += d * d;
        v[k] = s0; v[k + 4] = s1;
    }

    const unsigned FULL = 0xFFFFFFFFu;
    // off=16: fold sp_k with sn_k (8 shfl)
    float w[4];
    #pragma unroll
    for (int k = 0; k < 4; k++) {
        float a  = v[k], b = v[k + 4];
        float a2 = __shfl_xor_sync(FULL, a, 16);
        float b2 = __shfl_xor_sync(FULL, b, 16);
        w[k] = (lane & 16) ? (b + b2) : (a + a2);
    }
    // off=8: fold k with k+2 (4 shfl)
    float x[2];
    #pragma unroll
    for (int k = 0; k < 2; k++) {
        float a  = w[k], b = w[k + 2];
        float a2 = __shfl_xor_sync(FULL, a, 8);
        float b2 = __shfl_xor_sync(FULL, b, 8);
        x[k] = (lane & 8) ? (b + b2) : (a + a2);
    }
    // off=4: fold x0 with x1 (2 shfl)
    {
        float a  = x[0], b = x[1];
        float a2 = __shfl_xor_sync(FULL, a, 4);
        float b2 = __shfl_xor_sync(FULL, b, 4);
        x[0] = (lane & 4) ? (b + b2) : (a + a2);
    }
    // off=2,1: plain butterfly (2 shfl)
    x[0] += __shfl_xor_sync(FULL, x[0], 2);
    x[0] += __shfl_xor_sync(FULL, x[0], 1);

    const float r  = fsqrt_approx(x[0]);
    const float rn = __shfl_xor_sync(FULL, r, 16);

    const int  trip  = (((lane >> 3) & 1) << 1) | ((lane >> 2) & 1);
    const bool kind0 = (lane & 16) == 0;
    const bool valid = (t + trip) < T;

    const float loss = fmaxf(r - rn + MARGIN, 0.0f);
    return (kind0 && valid) ? 0.25f * loss : 0.0f;
}

__global__ void __launch_bounds__(TPB)
triplet_kernel(const float* __restrict__ emb,
               const int*   __restrict__ a_idx,
               const int*   __restrict__ p_idx,
               const int*   __restrict__ n_idx,
               float* __restrict__ out,
               int T, int nblocks)
{
    extern __shared__ char smem[];
    const int lane   = threadIdx.x & 31;
    const int w      = threadIdx.x >> 5;
    const int gw     = blockIdx.x * WPB + w;
    const int stride = nblocks * WPB * BATCH;   // strided -> L2 temporal reuse
    const uint32_t warp_smem = smem_u32(smem) + w * WARP_B;

    float acc = 0.0f;

    const int base_t = gw * BATCH;
    if (base_t < T) {
        const int n_it = (T - base_t + stride - 1) / stride;
        const int nfill = (n_it < STAGES) ? n_it : STAGES;

        for (int s = 0; s < nfill; s++) {
            IdxSet S;
            load_indices(a_idx, p_idx, n_idx, base_t + s * stride, T, S);
            fill_stage(emb, S, lane, warp_smem, s);
        }

        // 2x-unrolled ping-pong over two index register sets (no copies).
        IdxSet ia_, ib_;
        if (n_it > STAGES)
            load_indices(a_idx, p_idx, n_idx, base_t + STAGES * stride, T, ia_);

        int t = base_t;
        int i = 0;
        while (i < n_it) {
            {
                const int tnf = t + (STAGES + 1) * stride;
                if (tnf < T)
                    load_indices(a_idx, p_idx, n_idx, tnf, T, ib_);

                if (i < n_it - 1) CP_WAIT(1);
                else              CP_WAIT(0);

                acc += compute_stage(t, T, lane, warp_smem, i & 1);

                if (t + STAGES * stride < T)
                    fill_stage(emb, ia_, lane, warp_smem, i & 1);

                i++; t += stride;
                if (i >= n_it) break;
            }
            {
                const int tnf = t + (STAGES + 1) * stride;
                if (tnf < T)
                    load_indices(a_idx, p_idx, n_idx, tnf, T, ia_);

                if (i < n_it - 1) CP_WAIT(1);
                else              CP_WAIT(0);

                acc += compute_stage(t, T, lane, warp_smem, i & 1);

                if (t + STAGES * stride < T)
                    fill_stage(emb, ib_, lane, warp_smem, i & 1);

                i++; t += stride;
            }
        }
    }

    // Final per-warp reduction of the non-uniform pre-weighted accumulator.
    const unsigned FULL = 0xFFFFFFFFu;
    #pragma unroll
    for (int off = 16; off > 0; off >>= 1)
        acc += __shfl_xor_sync(FULL, acc, off);

    // ---- block reduction, fixed order -> deterministic ----
    __shared__ float ws[WPB];
    __shared__ bool  is_last;
    if (lane == 0) ws[w] = acc;
    __syncthreads();
    if (threadIdx.x == 0) {
        float s = 0.0f;
        #pragma unroll
        for (int i2 = 0; i2 < WPB; i2++) s += ws[i2];
        g_partial[blockIdx.x] = s;
        __threadfence();
        unsigned int done = atomicAdd(&g_ticket, 1u);
        is_last = (done == (unsigned)(nblocks - 1));
    }
    __syncthreads();

    // ---- last block folds all partials: deterministic fixed-order tree ----
    if (is_last) {
        __shared__ float sh[TPB];
        float s = 0.0f;
        for (int i2 = threadIdx.x; i2 < nblocks; i2 += TPB)
            s += g_partial[i2];
        sh[threadIdx.x] = s;
        __syncthreads();
        #pragma unroll
        for (int off = TPB / 2; off > 0; off >>= 1) {
            if (threadIdx.x < off) sh[threadIdx.x] += sh[threadIdx.x + off];
            __syncthreads();
        }
        if (threadIdx.x == 0) {
            out[0] = sh[0] / (float)T;
            g_ticket = 0;          // reset for next graph replay
        }
    }
}

extern "C" void kernel_launch(void* const* d_in, const int* in_sizes, int n_in,
                              void* d_out, int out_size)
{
    const float* emb   = (const float*)d_in[0];
    const int*   a_idx = (const int*)d_in[2];
    const int*   p_idx = (const int*)d_in[3];
    const int*   n_idx = (const int*)d_in[4];
    float*       out   = (float*)d_out;

    const int T = in_sizes[2];

    cudaFuncSetAttribute(triplet_kernel,
                         cudaFuncAttributeMaxDynamicSharedMemorySize, SMEM_B);

    int dev = 0, nsm = 148, bpm = 4;
    cudaGetDevice(&dev);
    cudaDeviceGetAttribute(&nsm, cudaDevAttrMultiProcessorCount, dev);
    cudaOccupancyMaxActiveBlocksPerMultiprocessor(&bpm, triplet_kernel, TPB, SMEM_B);
    if (bpm < 1) bpm = 1;
    int nblocks = nsm * bpm;
    if (nblocks > MAXBLK) nblocks = MAXBLK;

    triplet_kernel<<<nblocks, TPB, SMEM_B>>>(emb, a_idx, p_idx, n_idx, out, T, nblocks);
}